// round 5
// baseline (speedup 1.0000x reference)
#include <cuda_runtime.h>
#include <math_constants.h>

// x: [4,16,8192] f32 ; weights1: [16,16,64] f32 ; out: [4,16,4097] f32
#define NN    8192
#define MM    64
#define N2    4097
#define NPART 128
#define NBLK  148
#define NTHR  512

// -------- device scratch --------
__device__ float g_P[NPART * 64 * 64];    // stage-1 partials (2 MB) [p][r*64+k]
__device__ float g_hq[MM * 256];          // hq transposed: [m][u], u = i*16+o
__device__ float g_u[64 * 64];            // u[r][m]
__device__ float g_v[64 * 64];            // v[r][m]
__device__ float g_zT[MM * 64];           // z transposed: [m'][r]

// -------- grid barrier (all 148 blocks resident: 1 CTA/SM) --------
__device__ unsigned g_bar_count = 0;
__device__ unsigned g_bar_gen   = 0;

__device__ __forceinline__ void grid_bar()
{
    __syncthreads();
    if (threadIdx.x == 0) {
        __threadfence();
        unsigned gen = *(volatile unsigned*)&g_bar_gen;
        unsigned arrived = atomicAdd(&g_bar_count, 1u) + 1u;
        if (arrived == (unsigned)NBLK) {
            g_bar_count = 0;
            __threadfence();
            *(volatile unsigned*)&g_bar_gen = gen + 1u;
        } else {
            while (*(volatile unsigned*)&g_bar_gen == gen) __nanosleep(32);
        }
        __threadfence();
    }
    __syncthreads();
}

// -------- shared memory union --------
struct SmemA {
    float Xs[64][68];
    float Cs[64][68];
    float ws[16][64];
    float v64[64];
};
struct SmemR {
    float red[8][64];
    float Ys[64];
    float hps[64];
    float v64[64];
};
struct SmemZ {
    float u16[16][68];
    float v16[16][68];
    float hzs[16][68];
    float v64[64];
};
struct SmemC {
    float zs[64][68];
    float Cs[64][36];
};
union SmemU { SmemA a; SmemR r; SmemZ z; SmemC c; };

__global__ __launch_bounds__(NTHR, 1)
void k_fused(const float* __restrict__ x, const float* __restrict__ w,
             float* __restrict__ out)
{
    __shared__ SmemU sm;
    const int blk = blockIdx.x;
    const int tid = threadIdx.x;

    // ================= PHASE A: GEMM partials + hq =================
    if (blk < NPART) {
        const int n0 = blk * 64;
        #pragma unroll
        for (int q = 0; q < 2; q++) {
            int idx = tid + q * NTHR;            // 0..1023
            int row = idx >> 4;
            int c4  = (idx & 15) * 4;
            float4 v = *reinterpret_cast<const float4*>(x + row * NN + n0 + c4);
            sm.a.Xs[c4 + 0][row] = v.x;
            sm.a.Xs[c4 + 1][row] = v.y;
            sm.a.Xs[c4 + 2][row] = v.z;
            sm.a.Xs[c4 + 3][row] = v.w;
        }
        // cas table via rotation recurrence (8 entries/thread)
        {
            const float W0 = 2.0f * CUDART_PI_F / 8192.0f;
            const int nl = tid >> 3;
            const int k0 = (tid & 7) * 8;
            unsigned nm = (unsigned)(n0 + nl) & 8191u;
            unsigned t0 = (nm * (unsigned)k0) & 8191u;
            float s0, c0, sd, cd;
            __sincosf((float)t0 * W0, &s0, &c0);
            __sincosf((float)nm * W0, &sd, &cd);
            float c = c0, s = s0;
            #pragma unroll
            for (int j = 0; j < 8; j++) {
                sm.a.Cs[nl][k0 + j] = c + s;
                float cn = fmaf(c, cd, -s * sd);
                float sn = fmaf(s, cd,  c * sd);
                c = cn; s = sn;
            }
        }
        __syncthreads();

        // split-n within block
        const int half = tid >> 8;
        const int tid2 = tid & 255;
        const int kq = tid2 & 15, rq = tid2 >> 4;
        const int r0 = rq * 4, k0 = kq * 4;
        const int nb = half * 32;
        float acc[4][4] = {};
        #pragma unroll
        for (int j = 0; j < 32; j++) {
            int nl = nb + j;
            float4 xv = *reinterpret_cast<const float4*>(&sm.a.Xs[nl][r0]);
            float4 cv = *reinterpret_cast<const float4*>(&sm.a.Cs[nl][k0]);
            float xr[4] = {xv.x, xv.y, xv.z, xv.w};
            float ck[4] = {cv.x, cv.y, cv.z, cv.w};
            #pragma unroll
            for (int a = 0; a < 4; a++)
                #pragma unroll
                for (int b = 0; b < 4; b++)
                    acc[a][b] = fmaf(xr[a], ck[b], acc[a][b]);
        }
        __syncthreads();
        float4* scratch = reinterpret_cast<float4*>(&sm.a.Xs[0][0]); // [4][256]
        if (half == 1) {
            #pragma unroll
            for (int a = 0; a < 4; a++)
                scratch[a * 256 + tid2] =
                    make_float4(acc[a][0], acc[a][1], acc[a][2], acc[a][3]);
        }
        __syncthreads();
        if (half == 0) {
            float* P = g_P + blk * 4096;
            #pragma unroll
            for (int a = 0; a < 4; a++) {
                float4 o = scratch[a * 256 + tid2];
                o.x += acc[a][0]; o.y += acc[a][1];
                o.z += acc[a][2]; o.w += acc[a][3];
                *reinterpret_cast<float4*>(P + (r0 + a) * 64 + k0) = o;
            }
        }
    } else if (blk < NPART + 16) {
        const int u0 = (blk - NPART) * 16;
        #pragma unroll
        for (int q = 0; q < 2; q++) {
            int idx = tid + q * NTHR;
            sm.a.ws[idx >> 6][idx & 63] = w[u0 * 64 + idx];
        }
        if (tid < 64) {
            const float W1 = 2.0f * CUDART_PI_F / 64.0f;
            float s, c;
            __sincosf((float)tid * W1, &s, &c);
            sm.a.v64[tid] = c + s;
        }
        __syncthreads();
        #pragma unroll
        for (int q = 0; q < 8; q++) {
            int idx = tid + q * NTHR;
            int j = idx >> 6, m = idx & 63;
            sm.a.Cs[j][m] = sm.a.v64[(j * m) & 63];
        }
        __syncthreads();
        #pragma unroll
        for (int q = 0; q < 2; q++) {
            int idx = tid + q * NTHR;
            int ul = idx >> 6, m = idx & 63;
            float acc = 0.f;
            #pragma unroll
            for (int j = 0; j < 64; j++)
                acc = fmaf(sm.a.ws[ul][j], sm.a.Cs[j][m], acc);
            g_hq[m * 256 + u0 + ul] = acc;
        }
    }

    grid_bar();

    // ================= PHASE R: per-row reduce + hp + (u,v) =================
    // block = row r (64 blocks). Reads 128 partials x 64 k, coalesced.
    if (blk < 64) {
        const int r = blk;
        if (tid < 64) {
            const float W1 = 2.0f * CUDART_PI_F / 64.0f;
            float s, c;
            __sincosf((float)tid * W1, &s, &c);
            sm.r.v64[tid] = c + s;
        }
        {
            const int pg = tid >> 6;          // 0..7 partial-groups
            const int k  = tid & 63;
            const float* P = g_P + r * 64 + k + pg * 16 * 4096;
            float a0 = 0.f, a1 = 0.f, a2 = 0.f, a3 = 0.f;
            #pragma unroll
            for (int p = 0; p < 16; p += 4) {
                a0 += P[(p + 0) * 4096];
                a1 += P[(p + 1) * 4096];
                a2 += P[(p + 2) * 4096];
                a3 += P[(p + 3) * 4096];
            }
            sm.r.red[pg][k] = (a0 + a1) + (a2 + a3);
        }
        __syncthreads();
        if (tid < 64) {
            float s = 0.f;
            #pragma unroll
            for (int g = 0; g < 8; g++) s += sm.r.red[g][tid];
            sm.r.Ys[tid] = s;
        }
        __syncthreads();
        if (tid < 64) {   // m = tid: hp[r][m]
            const int m = tid;
            float acc = 0.f;
            #pragma unroll
            for (int k = 0; k < 64; k++)
                acc = fmaf(sm.r.Ys[k], sm.r.v64[(k * m) & 63], acc);
            sm.r.hps[m] = acc;
        }
        __syncthreads();
        if (tid < 64) {
            const int m = tid, mr = (64 - m) & 63;
            float a = sm.r.hps[m], b2 = sm.r.hps[mr];
            g_u[r * 64 + m] = a + b2;
            g_v[r * 64 + m] = a - b2;
        }
    }

    grid_bar();

    // ================= PHASE Z: hz + z (4 blocks, one per batch) ============
    if (blk < 4) {
        const int b = blk;
        if (tid < 64) {
            const float W1 = 2.0f * CUDART_PI_F / 64.0f;
            float s, c;
            __sincosf((float)tid * W1, &s, &c);
            sm.z.v64[tid] = c + s;
        }
        #pragma unroll
        for (int q = 0; q < 2; q++) {
            int idx = tid + q * NTHR;   // 0..1023
            int i = idx >> 6, m = idx & 63;
            sm.z.u16[i][m] = g_u[b * 1024 + idx];
            sm.z.v16[i][m] = g_v[b * 1024 + idx];
        }
        __syncthreads();
        #pragma unroll
        for (int q = 0; q < 2; q++) {
            int idx = tid + q * NTHR;
            int m = idx >> 4, o = idx & 15;
            int mr = (64 - m) & 63;
            const float* hq1 = g_hq + m  * 256 + o;
            const float* hq2 = g_hq + mr * 256 + o;
            float acc = 0.f;
            #pragma unroll
            for (int i = 0; i < 16; i++) {
                acc = fmaf(sm.z.u16[i][m], hq1[i * 16], acc);
                acc = fmaf(sm.z.v16[i][m], hq2[i * 16], acc);
            }
            sm.z.hzs[o][m] = 0.5f * acc;
        }
        __syncthreads();
        #pragma unroll
        for (int q = 0; q < 2; q++) {
            int idx = tid + q * NTHR;
            int o = idx >> 6, mp = idx & 63;
            float acc = 0.f;
            #pragma unroll
            for (int m = 0; m < 64; m++)
                acc = fmaf(sm.z.hzs[o][m], sm.z.v64[(m * mp) & 63], acc);
            g_zT[mp * 64 + b * 16 + o] = acc * (1.0f / 4096.0f);
        }
    }

    grid_bar();

    // ================= PHASE C: final DHT (129 blocks) =================
    if (blk < 129) {
        const int kbase = blk * 32;
        #pragma unroll
        for (int q = 0; q < 2; q++) {
            int i4 = tid + q * NTHR;
            float4 v = *reinterpret_cast<const float4*>(g_zT + i4 * 4);
            int f = i4 * 4;
            *reinterpret_cast<float4*>(&sm.c.zs[f >> 6][f & 63]) = v;
        }
        {
            const float W2 = 2.0f * CUDART_PI_F / 4097.0f;
            const int mm = tid >> 3;
            const int kt0 = (tid & 7) * 4;
            int k0 = kbase + kt0;
            int t0 = (mm * k0) % 4097;
            float s0, c0, sd, cd;
            __sincosf((float)t0 * W2, &s0, &c0);
            __sincosf((float)mm * W2, &sd, &cd);
            float c = c0, s = s0;
            #pragma unroll
            for (int j = 0; j < 4; j++) {
                sm.c.Cs[mm][kt0 + j] = c + s;
                float cn = fmaf(c, cd, -s * sd);
                float sn = fmaf(s, cd,  c * sd);
                c = cn; s = sn;
            }
        }
        __syncthreads();

        const int ktq = tid & 31;
        const int rq  = tid >> 5;
        const int r0  = rq * 4;
        const int k   = kbase + ktq;
        float a0 = 0.f, a1 = 0.f, a2 = 0.f, a3 = 0.f;
        #pragma unroll
        for (int mm = 0; mm < 64; mm++) {
            float4 zv = *reinterpret_cast<const float4*>(&sm.c.zs[mm][r0]);
            float cv = sm.c.Cs[mm][ktq];
            a0 = fmaf(zv.x, cv, a0);
            a1 = fmaf(zv.y, cv, a1);
            a2 = fmaf(zv.z, cv, a2);
            a3 = fmaf(zv.w, cv, a3);
        }
        const float SCL = 1.0f / 262208.0f;
        if (k < N2) {
            out[(r0 + 0) * N2 + k] = a0 * SCL;
            out[(r0 + 1) * N2 + k] = a1 * SCL;
            out[(r0 + 2) * N2 + k] = a2 * SCL;
            out[(r0 + 3) * N2 + k] = a3 * SCL;
        }
    }
}

// ============================================================
extern "C" void kernel_launch(void* const* d_in, const int* in_sizes, int n_in,
                              void* d_out, int out_size)
{
    const float* x = (const float*)d_in[0];   // [4,16,8192]
    const float* w = (const float*)d_in[1];   // [16,16,64]
    float* out = (float*)d_out;               // [4,16,4097]

    k_fused<<<NBLK, NTHR>>>(x, w, out);
}